// round 4
// baseline (speedup 1.0000x reference)
#include <cuda_runtime.h>
#include <cuda_bf16.h>
#include <cstdint>

#define D 128
#define GN_EPS 1e-5f
#define MAXN 50000
#define MAXE 800000

// ---------------- scratch ----------------
__device__ float g_t[(size_t)MAXN * D];   // GEMM output, pre-scaled by dinv[row]
__device__ float g_h[(size_t)MAXN * D];   // aggregated layer output
__device__ int   g_cnt[MAXN];             // in-degree (excluding self loop)
__device__ float g_dinv[MAXN];
__device__ int   g_rowp[MAXN];            // CSR row start
__device__ int   g_cur[MAXN];             // fill cursor
__device__ int   g_csr[MAXE];             // src ids grouped by dst
__device__ int   g_bsum[64];              // scan block totals
__device__ float g_cs[D];
__device__ float g_css[D];
__device__ float g_scale[D];
__device__ float g_shift[D];

// ---------------- degree / CSR build ----------------
__global__ void zero_cnt_k(int n) {
    int i = blockIdx.x * blockDim.x + threadIdx.x;
    if (i < n) g_cnt[i] = 0;
    if (blockIdx.x == 0 && threadIdx.x < D) {
        g_cs[threadIdx.x] = 0.0f;
        g_css[threadIdx.x] = 0.0f;
    }
}

__global__ void hist_k(const int* __restrict__ dst, int e) {
    int i = blockIdx.x * blockDim.x + threadIdx.x;
    if (i < e) atomicAdd(&g_cnt[dst[i]], 1);
}

__global__ void dinv_k(int n) {
    int i = blockIdx.x * blockDim.x + threadIdx.x;
    if (i < n) g_dinv[i] = rsqrtf((float)g_cnt[i] + 1.0f);
}

// phase 1: per-block inclusive scan of 1024-element tiles
__global__ void scan1_k(int n) {
    __shared__ int wsum[32];
    int i = blockIdx.x * 1024 + threadIdx.x;
    int lane = threadIdx.x & 31, w = threadIdx.x >> 5;
    int v = (i < n) ? g_cnt[i] : 0;
    int x = v;
#pragma unroll
    for (int off = 1; off < 32; off <<= 1) {
        int t = __shfl_up_sync(0xFFFFFFFFu, x, off);
        if (lane >= off) x += t;
    }
    if (lane == 31) wsum[w] = x;
    __syncthreads();
    if (w == 0) {
        int s = wsum[lane];
#pragma unroll
        for (int off = 1; off < 32; off <<= 1) {
            int t = __shfl_up_sync(0xFFFFFFFFu, s, off);
            if (lane >= off) s += t;
        }
        wsum[lane] = s;
    }
    __syncthreads();
    int base = (w > 0) ? wsum[w - 1] : 0;
    int excl = base + x - v;
    if (i < n) g_rowp[i] = excl;
    if (threadIdx.x == 1023) g_bsum[blockIdx.x] = base + x;
}

// phase 2: serial exclusive scan of block totals (<=64 values)
__global__ void scan2_k(int nb) {
    if (threadIdx.x == 0) {
        int run = 0;
        for (int b = 0; b < nb; b++) {
            int t = g_bsum[b];
            g_bsum[b] = run;
            run += t;
        }
    }
}

// phase 3: add block offsets
__global__ void scan3_k(int n) {
    int i = blockIdx.x * blockDim.x + threadIdx.x;
    if (i < n) {
        int r = g_rowp[i] + g_bsum[i >> 10];
        g_rowp[i] = r;
        g_cur[i] = r;
    }
}

__global__ void fill_k(const int* __restrict__ src, const int* __restrict__ dst, int e) {
    int i = blockIdx.x * blockDim.x + threadIdx.x;
    if (i < e) {
        int pos = atomicAdd(&g_cur[dst[i]], 1);
        g_csr[pos] = src[i];
    }
}

// ---------------- SGEMM: [M,128] @ [128,128] -> g_t (scaled by dinv) ----------
#define BM 64
#define BK 32
__global__ void __launch_bounds__(256) gemm_k(const float* __restrict__ A,
                                              const float* __restrict__ W,
                                              int M, int transform) {
    __shared__ float xs[BM][BK + 1];
    __shared__ float ws[BK][D];
    __shared__ float s_sc[D], s_sh[D];
    const float* __restrict__ a_ptr = A ? A : g_h;

    int tid  = threadIdx.x;
    int tcol = tid & 31;
    int trow = tid >> 5;
    int row0 = blockIdx.x * BM;

    if (transform && tid < D) {
        s_sc[tid] = g_scale[tid];
        s_sh[tid] = g_shift[tid];
    }
    if (transform) __syncthreads();

    float acc[8][4];
#pragma unroll
    for (int i = 0; i < 8; i++)
#pragma unroll
        for (int j = 0; j < 4; j++) acc[i][j] = 0.0f;

    for (int kk = 0; kk < D; kk += BK) {
#pragma unroll
        for (int i = 0; i < 8; i++) {
            int idx = tid + i * 256;
            int r = idx >> 5, k = idx & 31;
            int gr = row0 + r;
            float v = (gr < M) ? a_ptr[(size_t)gr * D + kk + k] : 0.0f;
            if (transform) v = fmaxf(fmaf(v, s_sc[kk + k], s_sh[kk + k]), 0.0f);
            xs[r][k] = v;
        }
#pragma unroll
        for (int i = 0; i < 16; i++) {
            int idx = tid + i * 256;
            int k = idx >> 7, c = idx & 127;
            ws[k][c] = W[(size_t)(kk + k) * D + c];
        }
        __syncthreads();
#pragma unroll
        for (int k = 0; k < BK; k++) {
            float4 wv = *(const float4*)&ws[k][tcol * 4];
#pragma unroll
            for (int i = 0; i < 8; i++) {
                float a = xs[trow * 8 + i][k];
                acc[i][0] += a * wv.x;
                acc[i][1] += a * wv.y;
                acc[i][2] += a * wv.z;
                acc[i][3] += a * wv.w;
            }
        }
        __syncthreads();
    }
#pragma unroll
    for (int i = 0; i < 8; i++) {
        int gr = row0 + trow * 8 + i;
        if (gr < M) {
            float di = g_dinv[gr];
            float4 o = make_float4(acc[i][0] * di, acc[i][1] * di,
                                   acc[i][2] * di, acc[i][3] * di);
            *(float4*)&g_t[(size_t)gr * D + tcol * 4] = o;
        }
    }
}

// ---------------- CSR gather aggregation ----------------
// MODE 0: write g_h, accumulate GraphNorm stats.
// MODE 1: fuse output head (h @ Wout + bout) -> out, no g_h write.
template <int MODE>
__global__ void __launch_bounds__(256) gather_k(const float* __restrict__ b,
                                                const float* __restrict__ Wout,
                                                const float* __restrict__ bout,
                                                float* __restrict__ out, int n) {
    int lane = threadIdx.x & 31;
    int warp = (blockIdx.x * blockDim.x + threadIdx.x) >> 5;
    int nwarps = (gridDim.x * blockDim.x) >> 5;

    float4 bb = *(const float4*)&b[lane * 4];
    float4 ssum = make_float4(0, 0, 0, 0);
    float4 ssq  = make_float4(0, 0, 0, 0);
    float w0[4], w1[4];
    float bo0 = 0.0f, bo1 = 0.0f;
    if (MODE == 1) {
#pragma unroll
        for (int j = 0; j < 4; j++) {
            w0[j] = __ldg(&Wout[(lane * 4 + j) * 2 + 0]);
            w1[j] = __ldg(&Wout[(lane * 4 + j) * 2 + 1]);
        }
        bo0 = __ldg(&bout[0]);
        bo1 = __ldg(&bout[1]);
    }

    for (int d = warp; d < n; d += nwarps) {
        float4 acc = __ldg((const float4*)&g_t[(size_t)d * D + lane * 4]);  // self loop
        int beg = g_rowp[d];
        int end = beg + g_cnt[d];
        int e = beg;
        for (; e + 4 <= end; e += 4) {
            int s0 = __ldg(&g_csr[e]);
            int s1 = __ldg(&g_csr[e + 1]);
            int s2 = __ldg(&g_csr[e + 2]);
            int s3 = __ldg(&g_csr[e + 3]);
            float4 v0 = __ldg((const float4*)&g_t[(size_t)s0 * D + lane * 4]);
            float4 v1 = __ldg((const float4*)&g_t[(size_t)s1 * D + lane * 4]);
            float4 v2 = __ldg((const float4*)&g_t[(size_t)s2 * D + lane * 4]);
            float4 v3 = __ldg((const float4*)&g_t[(size_t)s3 * D + lane * 4]);
            acc.x += (v0.x + v1.x) + (v2.x + v3.x);
            acc.y += (v0.y + v1.y) + (v2.y + v3.y);
            acc.z += (v0.z + v1.z) + (v2.z + v3.z);
            acc.w += (v0.w + v1.w) + (v2.w + v3.w);
        }
        for (; e < end; e++) {
            int s = __ldg(&g_csr[e]);
            float4 v = __ldg((const float4*)&g_t[(size_t)s * D + lane * 4]);
            acc.x += v.x; acc.y += v.y; acc.z += v.z; acc.w += v.w;
        }
        float di = g_dinv[d];
        acc.x = fmaf(acc.x, di, bb.x);
        acc.y = fmaf(acc.y, di, bb.y);
        acc.z = fmaf(acc.z, di, bb.z);
        acc.w = fmaf(acc.w, di, bb.w);

        if (MODE == 0) {
            *(float4*)&g_h[(size_t)d * D + lane * 4] = acc;
            ssum.x += acc.x; ssum.y += acc.y; ssum.z += acc.z; ssum.w += acc.w;
            ssq.x += acc.x * acc.x; ssq.y += acc.y * acc.y;
            ssq.z += acc.z * acc.z; ssq.w += acc.w * acc.w;
        } else {
            float a0 = acc.x * w0[0] + acc.y * w0[1] + acc.z * w0[2] + acc.w * w0[3];
            float a1 = acc.x * w1[0] + acc.y * w1[1] + acc.z * w1[2] + acc.w * w1[3];
#pragma unroll
            for (int off = 16; off > 0; off >>= 1) {
                a0 += __shfl_down_sync(0xFFFFFFFFu, a0, off);
                a1 += __shfl_down_sync(0xFFFFFFFFu, a1, off);
            }
            if (lane == 0) {
                out[(size_t)d * 2 + 0] = a0 + bo0;
                out[(size_t)d * 2 + 1] = a1 + bo1;
            }
        }
    }

    if (MODE == 0) {
        atomicAdd(&g_cs[lane * 4 + 0], ssum.x);
        atomicAdd(&g_cs[lane * 4 + 1], ssum.y);
        atomicAdd(&g_cs[lane * 4 + 2], ssum.z);
        atomicAdd(&g_cs[lane * 4 + 3], ssum.w);
        atomicAdd(&g_css[lane * 4 + 0], ssq.x);
        atomicAdd(&g_css[lane * 4 + 1], ssq.y);
        atomicAdd(&g_css[lane * 4 + 2], ssq.z);
        atomicAdd(&g_css[lane * 4 + 3], ssq.w);
    }
}

// ---------------- GraphNorm finalize (also re-zeroes stats) ----------------
__global__ void finalize_k(const float* __restrict__ w, const float* __restrict__ b,
                           const float* __restrict__ a, int n) {
    int c = threadIdx.x;
    float inv_n = 1.0f / (float)n;
    float m = g_cs[c] * inv_n;
    float msq = g_css[c] * inv_n;
    float al = a[c];
    float var = msq - (2.0f * al - al * al) * m * m;
    float sc = rsqrtf(var + GN_EPS) * w[c];
    g_scale[c] = sc;
    g_shift[c] = b[c] - al * m * sc;
    g_cs[c] = 0.0f;
    g_css[c] = 0.0f;
}

// ---------------- launch ----------------
extern "C" void kernel_launch(void* const* d_in, const int* in_sizes, int n_in,
                              void* d_out, int out_size) {
    const float* x    = (const float*)d_in[0];
    const int*   ei   = (const int*)d_in[1];
    const float* W1   = (const float*)d_in[2];
    const float* b1   = (const float*)d_in[3];
    const float* W2   = (const float*)d_in[4];
    const float* b2   = (const float*)d_in[5];
    const float* W3   = (const float*)d_in[6];
    const float* b3   = (const float*)d_in[7];
    const float* gn1w = (const float*)d_in[8];
    const float* gn1b = (const float*)d_in[9];
    const float* gn1a = (const float*)d_in[10];
    const float* gn2w = (const float*)d_in[11];
    const float* gn2b = (const float*)d_in[12];
    const float* gn2a = (const float*)d_in[13];
    const float* Wout = (const float*)d_in[14];
    const float* bout = (const float*)d_in[15];

    int n = in_sizes[0] / D;
    int e = in_sizes[1] / 2;
    const int* src = ei;
    const int* dst = ei + e;

    int node_blocks = (n + 255) / 256;
    int edge_blocks = (e + 255) / 256;
    int gemm_blocks = (n + BM - 1) / BM;
    int scan_blocks = (n + 1023) / 1024;
    int gather_blocks = 1024;     // grid-stride, ~56 warps/SM

    // CSR + degree build (once per launch, reused by all 3 layers)
    zero_cnt_k<<<node_blocks, 256>>>(n);
    hist_k<<<edge_blocks, 256>>>(dst, e);
    dinv_k<<<node_blocks, 256>>>(n);
    scan1_k<<<scan_blocks, 1024>>>(n);
    scan2_k<<<1, 32>>>(scan_blocks);
    scan3_k<<<node_blocks, 256>>>(n);
    fill_k<<<edge_blocks, 256>>>(src, dst, e);

    // ---- layer 1 ----
    gemm_k<<<gemm_blocks, 256>>>(x, W1, n, 0);
    gather_k<0><<<gather_blocks, 256>>>(b1, nullptr, nullptr, nullptr, n);
    finalize_k<<<1, 128>>>(gn1w, gn1b, gn1a, n);

    // ---- layer 2 ----
    gemm_k<<<gemm_blocks, 256>>>(nullptr, W2, n, 1);
    gather_k<0><<<gather_blocks, 256>>>(b2, nullptr, nullptr, nullptr, n);
    finalize_k<<<1, 128>>>(gn2w, gn2b, gn2a, n);

    // ---- layer 3 ----
    gemm_k<<<gemm_blocks, 256>>>(nullptr, W3, n, 1);
    gather_k<1><<<gather_blocks, 256>>>(b3, Wout, bout, (float*)d_out, n);
}

// round 6
// speedup vs baseline: 1.6824x; 1.6824x over previous
#include <cuda_runtime.h>
#include <cuda_bf16.h>
#include <cstdint>

#define D 128
#define GN_EPS 1e-5f
#define MAXN 50000
#define MAXE 800000
#define NPW 16          // nodes per warp in gather

// ---------------- scratch ----------------
__device__ float g_t[(size_t)MAXN * D];   // GEMM output, pre-scaled by dinv[row]
__device__ float g_h[(size_t)MAXN * D];   // aggregated layer output
__device__ int   g_cnt[MAXN];             // in-degree (excluding self loop)
__device__ float g_dinv[MAXN];
__device__ int   g_rowp[MAXN];            // CSR row start
__device__ int   g_cur[MAXN];             // fill cursor
__device__ int   g_csr[MAXE];             // src ids grouped by dst
__device__ int   g_bsum[64];              // scan block totals
__device__ float g_cs[D];
__device__ float g_css[D];
__device__ float g_scale[D];
__device__ float g_shift[D];

// ---------------- degree / CSR build ----------------
__global__ void zero_cnt_k(int n) {
    int i = blockIdx.x * blockDim.x + threadIdx.x;
    if (i < n) g_cnt[i] = 0;
    if (blockIdx.x == 0 && threadIdx.x < D) {
        g_cs[threadIdx.x] = 0.0f;
        g_css[threadIdx.x] = 0.0f;
    }
}

__global__ void hist_k(const int* __restrict__ dst, int e) {
    int i = blockIdx.x * blockDim.x + threadIdx.x;
    if (i < e) atomicAdd(&g_cnt[dst[i]], 1);
}

__global__ void dinv_k(int n) {
    int i = blockIdx.x * blockDim.x + threadIdx.x;
    if (i < n) g_dinv[i] = rsqrtf((float)g_cnt[i] + 1.0f);
}

// phase 1: per-block inclusive scan of 1024-element tiles
__global__ void scan1_k(int n) {
    __shared__ int wsum[32];
    int i = blockIdx.x * 1024 + threadIdx.x;
    int lane = threadIdx.x & 31, w = threadIdx.x >> 5;
    int v = (i < n) ? g_cnt[i] : 0;
    int x = v;
#pragma unroll
    for (int off = 1; off < 32; off <<= 1) {
        int t = __shfl_up_sync(0xFFFFFFFFu, x, off);
        if (lane >= off) x += t;
    }
    if (lane == 31) wsum[w] = x;
    __syncthreads();
    if (w == 0) {
        int s = wsum[lane];
#pragma unroll
        for (int off = 1; off < 32; off <<= 1) {
            int t = __shfl_up_sync(0xFFFFFFFFu, s, off);
            if (lane >= off) s += t;
        }
        wsum[lane] = s;
    }
    __syncthreads();
    int base = (w > 0) ? wsum[w - 1] : 0;
    int excl = base + x - v;
    if (i < n) g_rowp[i] = excl;
    if (threadIdx.x == 1023) g_bsum[blockIdx.x] = base + x;
}

// phase 2: serial exclusive scan of block totals (<=64 values)
__global__ void scan2_k(int nb) {
    if (threadIdx.x == 0) {
        int run = 0;
        for (int b = 0; b < nb; b++) {
            int t = g_bsum[b];
            g_bsum[b] = run;
            run += t;
        }
    }
}

// phase 3: add block offsets
__global__ void scan3_k(int n) {
    int i = blockIdx.x * blockDim.x + threadIdx.x;
    if (i < n) {
        int r = g_rowp[i] + g_bsum[i >> 10];
        g_rowp[i] = r;
        g_cur[i] = r;
    }
}

__global__ void fill_k(const int* __restrict__ src, const int* __restrict__ dst, int e) {
    int i = blockIdx.x * blockDim.x + threadIdx.x;
    if (i < e) {
        int pos = atomicAdd(&g_cur[dst[i]], 1);
        g_csr[pos] = src[i];
    }
}

// ---------------- SGEMM: [M,128] @ [128,128] -> g_t (scaled by dinv) ----------
#define BM 64
#define BK 32
__global__ void __launch_bounds__(256) gemm_k(const float* __restrict__ A,
                                              const float* __restrict__ W,
                                              int M, int transform) {
    __shared__ float xs[BM][BK + 1];
    __shared__ float ws[BK][D];
    __shared__ float s_sc[D], s_sh[D];
    const float* __restrict__ a_ptr = A ? A : g_h;

    int tid  = threadIdx.x;
    int tcol = tid & 31;
    int trow = tid >> 5;
    int row0 = blockIdx.x * BM;

    if (transform && tid < D) {
        s_sc[tid] = g_scale[tid];
        s_sh[tid] = g_shift[tid];
    }
    if (transform) __syncthreads();

    float acc[8][4];
#pragma unroll
    for (int i = 0; i < 8; i++)
#pragma unroll
        for (int j = 0; j < 4; j++) acc[i][j] = 0.0f;

    for (int kk = 0; kk < D; kk += BK) {
#pragma unroll
        for (int i = 0; i < 8; i++) {
            int idx = tid + i * 256;
            int r = idx >> 5, k = idx & 31;
            int gr = row0 + r;
            float v = (gr < M) ? a_ptr[(size_t)gr * D + kk + k] : 0.0f;
            if (transform) v = fmaxf(fmaf(v, s_sc[kk + k], s_sh[kk + k]), 0.0f);
            xs[r][k] = v;
        }
#pragma unroll
        for (int i = 0; i < 16; i++) {
            int idx = tid + i * 256;
            int k = idx >> 7, c = idx & 127;
            ws[k][c] = W[(size_t)(kk + k) * D + c];
        }
        __syncthreads();
#pragma unroll
        for (int k = 0; k < BK; k++) {
            float4 wv = *(const float4*)&ws[k][tcol * 4];
#pragma unroll
            for (int i = 0; i < 8; i++) {
                float a = xs[trow * 8 + i][k];
                acc[i][0] += a * wv.x;
                acc[i][1] += a * wv.y;
                acc[i][2] += a * wv.z;
                acc[i][3] += a * wv.w;
            }
        }
        __syncthreads();
    }
#pragma unroll
    for (int i = 0; i < 8; i++) {
        int gr = row0 + trow * 8 + i;
        if (gr < M) {
            float di = g_dinv[gr];
            float4 o = make_float4(acc[i][0] * di, acc[i][1] * di,
                                   acc[i][2] * di, acc[i][3] * di);
            *(float4*)&g_t[(size_t)gr * D + tcol * 4] = o;
        }
    }
}

// ---------------- CSR gather aggregation ----------------
// One warp owns NPW consecutive nodes (no grid-stride). 8-edge batches give
// 8 independent float4 row fetches in flight per warp.
// MODE 0: write g_h, accumulate GraphNorm stats.
// MODE 1: fuse output head (h @ Wout + bout) -> out, no g_h write.
template <int MODE>
__global__ void __launch_bounds__(256) gather_k(const float* __restrict__ b,
                                                const float* __restrict__ Wout,
                                                const float* __restrict__ bout,
                                                float* __restrict__ out, int n) {
    int lane = threadIdx.x & 31;
    int warp = (blockIdx.x * blockDim.x + threadIdx.x) >> 5;
    int d0 = warp * NPW;
    if (d0 >= n) return;
    int d1 = min(d0 + NPW, n);

    float4 bb = *(const float4*)&b[lane * 4];
    float4 ssum = make_float4(0, 0, 0, 0);
    float4 ssq  = make_float4(0, 0, 0, 0);
    float w0[4], w1[4];
    float bo0 = 0.0f, bo1 = 0.0f;
    if (MODE == 1) {
#pragma unroll
        for (int j = 0; j < 4; j++) {
            w0[j] = __ldg(&Wout[(lane * 4 + j) * 2 + 0]);
            w1[j] = __ldg(&Wout[(lane * 4 + j) * 2 + 1]);
        }
        bo0 = __ldg(&bout[0]);
        bo1 = __ldg(&bout[1]);
    }

    for (int d = d0; d < d1; d++) {
        float4 acc = *(const float4*)&g_t[(size_t)d * D + lane * 4];  // self loop
        int beg = g_rowp[d];
        int end = beg + g_cnt[d];
        int e = beg;
        for (; e + 8 <= end; e += 8) {
            int s[8];
#pragma unroll
            for (int j = 0; j < 8; j++) s[j] = g_csr[e + j];
            float4 v[8];
#pragma unroll
            for (int j = 0; j < 8; j++)
                v[j] = *(const float4*)&g_t[(size_t)s[j] * D + lane * 4];
            float4 p0, p1, p2, p3;
            p0.x = v[0].x + v[1].x; p0.y = v[0].y + v[1].y; p0.z = v[0].z + v[1].z; p0.w = v[0].w + v[1].w;
            p1.x = v[2].x + v[3].x; p1.y = v[2].y + v[3].y; p1.z = v[2].z + v[3].z; p1.w = v[2].w + v[3].w;
            p2.x = v[4].x + v[5].x; p2.y = v[4].y + v[5].y; p2.z = v[4].z + v[5].z; p2.w = v[4].w + v[5].w;
            p3.x = v[6].x + v[7].x; p3.y = v[6].y + v[7].y; p3.z = v[6].z + v[7].z; p3.w = v[6].w + v[7].w;
            acc.x += (p0.x + p1.x) + (p2.x + p3.x);
            acc.y += (p0.y + p1.y) + (p2.y + p3.y);
            acc.z += (p0.z + p1.z) + (p2.z + p3.z);
            acc.w += (p0.w + p1.w) + (p2.w + p3.w);
        }
        for (; e < end; e++) {
            int s = g_csr[e];
            float4 v = *(const float4*)&g_t[(size_t)s * D + lane * 4];
            acc.x += v.x; acc.y += v.y; acc.z += v.z; acc.w += v.w;
        }
        float di = g_dinv[d];
        acc.x = fmaf(acc.x, di, bb.x);
        acc.y = fmaf(acc.y, di, bb.y);
        acc.z = fmaf(acc.z, di, bb.z);
        acc.w = fmaf(acc.w, di, bb.w);

        if (MODE == 0) {
            *(float4*)&g_h[(size_t)d * D + lane * 4] = acc;
            ssum.x += acc.x; ssum.y += acc.y; ssum.z += acc.z; ssum.w += acc.w;
            ssq.x += acc.x * acc.x; ssq.y += acc.y * acc.y;
            ssq.z += acc.z * acc.z; ssq.w += acc.w * acc.w;
        } else {
            float a0 = acc.x * w0[0] + acc.y * w0[1] + acc.z * w0[2] + acc.w * w0[3];
            float a1 = acc.x * w1[0] + acc.y * w1[1] + acc.z * w1[2] + acc.w * w1[3];
#pragma unroll
            for (int off = 16; off > 0; off >>= 1) {
                a0 += __shfl_down_sync(0xFFFFFFFFu, a0, off);
                a1 += __shfl_down_sync(0xFFFFFFFFu, a1, off);
            }
            if (lane == 0) {
                out[(size_t)d * 2 + 0] = a0 + bo0;
                out[(size_t)d * 2 + 1] = a1 + bo1;
            }
        }
    }

    if (MODE == 0) {
        atomicAdd(&g_cs[lane * 4 + 0], ssum.x);
        atomicAdd(&g_cs[lane * 4 + 1], ssum.y);
        atomicAdd(&g_cs[lane * 4 + 2], ssum.z);
        atomicAdd(&g_cs[lane * 4 + 3], ssum.w);
        atomicAdd(&g_css[lane * 4 + 0], ssq.x);
        atomicAdd(&g_css[lane * 4 + 1], ssq.y);
        atomicAdd(&g_css[lane * 4 + 2], ssq.z);
        atomicAdd(&g_css[lane * 4 + 3], ssq.w);
    }
}

// ---------------- GraphNorm finalize (also re-zeroes stats) ----------------
__global__ void finalize_k(const float* __restrict__ w, const float* __restrict__ b,
                           const float* __restrict__ a, int n) {
    int c = threadIdx.x;
    float inv_n = 1.0f / (float)n;
    float m = g_cs[c] * inv_n;
    float msq = g_css[c] * inv_n;
    float al = a[c];
    float var = msq - (2.0f * al - al * al) * m * m;
    float sc = rsqrtf(var + GN_EPS) * w[c];
    g_scale[c] = sc;
    g_shift[c] = b[c] - al * m * sc;
    g_cs[c] = 0.0f;
    g_css[c] = 0.0f;
}

// ---------------- launch ----------------
extern "C" void kernel_launch(void* const* d_in, const int* in_sizes, int n_in,
                              void* d_out, int out_size) {
    const float* x    = (const float*)d_in[0];
    const int*   ei   = (const int*)d_in[1];
    const float* W1   = (const float*)d_in[2];
    const float* b1   = (const float*)d_in[3];
    const float* W2   = (const float*)d_in[4];
    const float* b2   = (const float*)d_in[5];
    const float* W3   = (const float*)d_in[6];
    const float* b3   = (const float*)d_in[7];
    const float* gn1w = (const float*)d_in[8];
    const float* gn1b = (const float*)d_in[9];
    const float* gn1a = (const float*)d_in[10];
    const float* gn2w = (const float*)d_in[11];
    const float* gn2b = (const float*)d_in[12];
    const float* gn2a = (const float*)d_in[13];
    const float* Wout = (const float*)d_in[14];
    const float* bout = (const float*)d_in[15];

    int n = in_sizes[0] / D;
    int e = in_sizes[1] / 2;
    const int* src = ei;
    const int* dst = ei + e;

    int node_blocks = (n + 255) / 256;
    int edge_blocks = (e + 255) / 256;
    int gemm_blocks = (n + BM - 1) / BM;
    int scan_blocks = (n + 1023) / 1024;
    int gather_blocks = (n + NPW * 8 - 1) / (NPW * 8);   // one warp per NPW nodes

    // CSR + degree build (once per launch, reused by all 3 layers)
    zero_cnt_k<<<node_blocks, 256>>>(n);
    hist_k<<<edge_blocks, 256>>>(dst, e);
    dinv_k<<<node_blocks, 256>>>(n);
    scan1_k<<<scan_blocks, 1024>>>(n);
    scan2_k<<<1, 32>>>(scan_blocks);
    scan3_k<<<node_blocks, 256>>>(n);
    fill_k<<<edge_blocks, 256>>>(src, dst, e);

    // ---- layer 1 ----
    gemm_k<<<gemm_blocks, 256>>>(x, W1, n, 0);
    gather_k<0><<<gather_blocks, 256>>>(b1, nullptr, nullptr, nullptr, n);
    finalize_k<<<1, 128>>>(gn1w, gn1b, gn1a, n);

    // ---- layer 2 ----
    gemm_k<<<gemm_blocks, 256>>>(nullptr, W2, n, 1);
    gather_k<0><<<gather_blocks, 256>>>(b2, nullptr, nullptr, nullptr, n);
    finalize_k<<<1, 128>>>(gn2w, gn2b, gn2a, n);

    // ---- layer 3 ----
    gemm_k<<<gemm_blocks, 256>>>(nullptr, W3, n, 1);
    gather_k<1><<<gather_blocks, 256>>>(b3, Wout, bout, (float*)d_out, n);
}

// round 7
// speedup vs baseline: 1.6832x; 1.0005x over previous
#include <cuda_runtime.h>
#include <cuda_fp16.h>
#include <cstdint>

#define D 128
#define GN_EPS 1e-5f
#define MAXN 50000
#define MAXE 800000
#define NPW 16          // nodes per warp in gather

// ---------------- scratch ----------------
__device__ __half g_t[(size_t)MAXN * D];  // GEMM output, fp16, pre-scaled by dinv[row]
__device__ float  g_h[(size_t)MAXN * D];  // aggregated layer output (fp32)
__device__ int    g_cnt[MAXN];            // in-degree (excluding self loop)
__device__ float  g_dinv[MAXN];
__device__ int    g_rowp[MAXN];           // CSR row start
__device__ int    g_cur[MAXN];            // fill cursor
__device__ int    g_csr[MAXE];            // src ids grouped by dst
__device__ int    g_bsum[64];             // scan block totals
__device__ float  g_cs[D];
__device__ float  g_css[D];
__device__ float  g_scale[D];
__device__ float  g_shift[D];

// ---------------- degree / CSR build ----------------
__global__ void zero_cnt_k(int n) {
    int i = blockIdx.x * blockDim.x + threadIdx.x;
    if (i < n) g_cnt[i] = 0;
    if (blockIdx.x == 0 && threadIdx.x < D) {
        g_cs[threadIdx.x] = 0.0f;
        g_css[threadIdx.x] = 0.0f;
    }
}

__global__ void hist_k(const int* __restrict__ dst, int e) {
    int i = blockIdx.x * blockDim.x + threadIdx.x;
    if (i < e) atomicAdd(&g_cnt[dst[i]], 1);
}

__global__ void dinv_k(int n) {
    int i = blockIdx.x * blockDim.x + threadIdx.x;
    if (i < n) g_dinv[i] = rsqrtf((float)g_cnt[i] + 1.0f);
}

// phase 1: per-block inclusive scan of 1024-element tiles
__global__ void scan1_k(int n) {
    __shared__ int wsum[32];
    int i = blockIdx.x * 1024 + threadIdx.x;
    int lane = threadIdx.x & 31, w = threadIdx.x >> 5;
    int v = (i < n) ? g_cnt[i] : 0;
    int x = v;
#pragma unroll
    for (int off = 1; off < 32; off <<= 1) {
        int t = __shfl_up_sync(0xFFFFFFFFu, x, off);
        if (lane >= off) x += t;
    }
    if (lane == 31) wsum[w] = x;
    __syncthreads();
    if (w == 0) {
        int s = wsum[lane];
#pragma unroll
        for (int off = 1; off < 32; off <<= 1) {
            int t = __shfl_up_sync(0xFFFFFFFFu, s, off);
            if (lane >= off) s += t;
        }
        wsum[lane] = s;
    }
    __syncthreads();
    int base = (w > 0) ? wsum[w - 1] : 0;
    int excl = base + x - v;
    if (i < n) g_rowp[i] = excl;
    if (threadIdx.x == 1023) g_bsum[blockIdx.x] = base + x;
}

// phase 2: serial exclusive scan of block totals (<=64 values)
__global__ void scan2_k(int nb) {
    if (threadIdx.x == 0) {
        int run = 0;
        for (int b = 0; b < nb; b++) {
            int t = g_bsum[b];
            g_bsum[b] = run;
            run += t;
        }
    }
}

// phase 3: add block offsets
__global__ void scan3_k(int n) {
    int i = blockIdx.x * blockDim.x + threadIdx.x;
    if (i < n) {
        int r = g_rowp[i] + g_bsum[i >> 10];
        g_rowp[i] = r;
        g_cur[i] = r;
    }
}

__global__ void fill_k(const int* __restrict__ src, const int* __restrict__ dst, int e) {
    int i = blockIdx.x * blockDim.x + threadIdx.x;
    if (i < e) {
        int pos = atomicAdd(&g_cur[dst[i]], 1);
        g_csr[pos] = src[i];
    }
}

// ---------------- SGEMM: [M,128] @ [128,128] -> g_t fp16 (scaled by dinv) ----
#define BM 64
#define BK 32
__global__ void __launch_bounds__(256) gemm_k(const float* __restrict__ A,
                                              const float* __restrict__ W,
                                              int M, int transform) {
    __shared__ float xs[BM][BK + 1];
    __shared__ float ws[BK][D];
    __shared__ float s_sc[D], s_sh[D];
    const float* __restrict__ a_ptr = A ? A : g_h;

    int tid  = threadIdx.x;
    int tcol = tid & 31;
    int trow = tid >> 5;
    int row0 = blockIdx.x * BM;

    if (transform && tid < D) {
        s_sc[tid] = g_scale[tid];
        s_sh[tid] = g_shift[tid];
    }
    if (transform) __syncthreads();

    float acc[8][4];
#pragma unroll
    for (int i = 0; i < 8; i++)
#pragma unroll
        for (int j = 0; j < 4; j++) acc[i][j] = 0.0f;

    for (int kk = 0; kk < D; kk += BK) {
#pragma unroll
        for (int i = 0; i < 8; i++) {
            int idx = tid + i * 256;
            int r = idx >> 5, k = idx & 31;
            int gr = row0 + r;
            float v = (gr < M) ? a_ptr[(size_t)gr * D + kk + k] : 0.0f;
            if (transform) v = fmaxf(fmaf(v, s_sc[kk + k], s_sh[kk + k]), 0.0f);
            xs[r][k] = v;
        }
#pragma unroll
        for (int i = 0; i < 16; i++) {
            int idx = tid + i * 256;
            int k = idx >> 7, c = idx & 127;
            ws[k][c] = W[(size_t)(kk + k) * D + c];
        }
        __syncthreads();
#pragma unroll
        for (int k = 0; k < BK; k++) {
            float4 wv = *(const float4*)&ws[k][tcol * 4];
#pragma unroll
            for (int i = 0; i < 8; i++) {
                float a = xs[trow * 8 + i][k];
                acc[i][0] += a * wv.x;
                acc[i][1] += a * wv.y;
                acc[i][2] += a * wv.z;
                acc[i][3] += a * wv.w;
            }
        }
        __syncthreads();
    }
#pragma unroll
    for (int i = 0; i < 8; i++) {
        int gr = row0 + trow * 8 + i;
        if (gr < M) {
            float di = g_dinv[gr];
            __half2 h0 = __floats2half2_rn(acc[i][0] * di, acc[i][1] * di);
            __half2 h1 = __floats2half2_rn(acc[i][2] * di, acc[i][3] * di);
            uint2 o;
            o.x = *(const unsigned*)&h0;
            o.y = *(const unsigned*)&h1;
            *(uint2*)&g_t[(size_t)gr * D + tcol * 4] = o;
        }
    }
}

// ---------------- CSR gather aggregation (fp16 rows, fp32 accumulation) ------
// One warp owns NPW consecutive nodes. 8-edge batches -> 8 independent uint2
// row fetches in flight (256B rows, 2 sectors each).
// MODE 0: write g_h (fp32), accumulate GraphNorm stats.
// MODE 1: fuse output head (h @ Wout + bout) -> out, no g_h write.
template <int MODE>
__global__ void __launch_bounds__(256) gather_k(const float* __restrict__ b,
                                                const float* __restrict__ Wout,
                                                const float* __restrict__ bout,
                                                float* __restrict__ out, int n) {
    int lane = threadIdx.x & 31;
    int warp = (blockIdx.x * blockDim.x + threadIdx.x) >> 5;
    int d0 = warp * NPW;
    if (d0 >= n) return;
    int d1 = min(d0 + NPW, n);

    float4 bb = *(const float4*)&b[lane * 4];
    float4 ssum = make_float4(0, 0, 0, 0);
    float4 ssq  = make_float4(0, 0, 0, 0);
    float w0[4], w1[4];
    float bo0 = 0.0f, bo1 = 0.0f;
    if (MODE == 1) {
#pragma unroll
        for (int j = 0; j < 4; j++) {
            w0[j] = __ldg(&Wout[(lane * 4 + j) * 2 + 0]);
            w1[j] = __ldg(&Wout[(lane * 4 + j) * 2 + 1]);
        }
        bo0 = __ldg(&bout[0]);
        bo1 = __ldg(&bout[1]);
    }

    for (int d = d0; d < d1; d++) {
        // self loop (row is fp16, pre-scaled)
        uint2 sr = *(const uint2*)&g_t[(size_t)d * D + lane * 4];
        float2 s0f = __half22float2(*(const __half2*)&sr.x);
        float2 s1f = __half22float2(*(const __half2*)&sr.y);
        float4 acc = make_float4(s0f.x, s0f.y, s1f.x, s1f.y);

        int beg = g_rowp[d];
        int end = beg + g_cnt[d];
        int e = beg;
        for (; e + 8 <= end; e += 8) {
            int s[8];
#pragma unroll
            for (int j = 0; j < 8; j++) s[j] = g_csr[e + j];
            uint2 v[8];
#pragma unroll
            for (int j = 0; j < 8; j++)
                v[j] = *(const uint2*)&g_t[(size_t)s[j] * D + lane * 4];
#pragma unroll
            for (int j = 0; j < 8; j++) {
                float2 a = __half22float2(*(const __half2*)&v[j].x);
                float2 c = __half22float2(*(const __half2*)&v[j].y);
                acc.x += a.x; acc.y += a.y; acc.z += c.x; acc.w += c.y;
            }
        }
        for (; e < end; e++) {
            int s = g_csr[e];
            uint2 vv = *(const uint2*)&g_t[(size_t)s * D + lane * 4];
            float2 a = __half22float2(*(const __half2*)&vv.x);
            float2 c = __half22float2(*(const __half2*)&vv.y);
            acc.x += a.x; acc.y += a.y; acc.z += c.x; acc.w += c.y;
        }
        float di = g_dinv[d];
        acc.x = fmaf(acc.x, di, bb.x);
        acc.y = fmaf(acc.y, di, bb.y);
        acc.z = fmaf(acc.z, di, bb.z);
        acc.w = fmaf(acc.w, di, bb.w);

        if (MODE == 0) {
            *(float4*)&g_h[(size_t)d * D + lane * 4] = acc;
            ssum.x += acc.x; ssum.y += acc.y; ssum.z += acc.z; ssum.w += acc.w;
            ssq.x += acc.x * acc.x; ssq.y += acc.y * acc.y;
            ssq.z += acc.z * acc.z; ssq.w += acc.w * acc.w;
        } else {
            float a0 = acc.x * w0[0] + acc.y * w0[1] + acc.z * w0[2] + acc.w * w0[3];
            float a1 = acc.x * w1[0] + acc.y * w1[1] + acc.z * w1[2] + acc.w * w1[3];
#pragma unroll
            for (int off = 16; off > 0; off >>= 1) {
                a0 += __shfl_down_sync(0xFFFFFFFFu, a0, off);
                a1 += __shfl_down_sync(0xFFFFFFFFu, a1, off);
            }
            if (lane == 0) {
                out[(size_t)d * 2 + 0] = a0 + bo0;
                out[(size_t)d * 2 + 1] = a1 + bo1;
            }
        }
    }

    if (MODE == 0) {
        atomicAdd(&g_cs[lane * 4 + 0], ssum.x);
        atomicAdd(&g_cs[lane * 4 + 1], ssum.y);
        atomicAdd(&g_cs[lane * 4 + 2], ssum.z);
        atomicAdd(&g_cs[lane * 4 + 3], ssum.w);
        atomicAdd(&g_css[lane * 4 + 0], ssq.x);
        atomicAdd(&g_css[lane * 4 + 1], ssq.y);
        atomicAdd(&g_css[lane * 4 + 2], ssq.z);
        atomicAdd(&g_css[lane * 4 + 3], ssq.w);
    }
}

// ---------------- GraphNorm finalize (also re-zeroes stats) ----------------
__global__ void finalize_k(const float* __restrict__ w, const float* __restrict__ b,
                           const float* __restrict__ a, int n) {
    int c = threadIdx.x;
    float inv_n = 1.0f / (float)n;
    float m = g_cs[c] * inv_n;
    float msq = g_css[c] * inv_n;
    float al = a[c];
    float var = msq - (2.0f * al - al * al) * m * m;
    float sc = rsqrtf(var + GN_EPS) * w[c];
    g_scale[c] = sc;
    g_shift[c] = b[c] - al * m * sc;
    g_cs[c] = 0.0f;
    g_css[c] = 0.0f;
}

// ---------------- launch ----------------
extern "C" void kernel_launch(void* const* d_in, const int* in_sizes, int n_in,
                              void* d_out, int out_size) {
    const float* x    = (const float*)d_in[0];
    const int*   ei   = (const int*)d_in[1];
    const float* W1   = (const float*)d_in[2];
    const float* b1   = (const float*)d_in[3];
    const float* W2   = (const float*)d_in[4];
    const float* b2   = (const float*)d_in[5];
    const float* W3   = (const float*)d_in[6];
    const float* b3   = (const float*)d_in[7];
    const float* gn1w = (const float*)d_in[8];
    const float* gn1b = (const float*)d_in[9];
    const float* gn1a = (const float*)d_in[10];
    const float* gn2w = (const float*)d_in[11];
    const float* gn2b = (const float*)d_in[12];
    const float* gn2a = (const float*)d_in[13];
    const float* Wout = (const float*)d_in[14];
    const float* bout = (const float*)d_in[15];

    int n = in_sizes[0] / D;
    int e = in_sizes[1] / 2;
    const int* src = ei;
    const int* dst = ei + e;

    int node_blocks = (n + 255) / 256;
    int edge_blocks = (e + 255) / 256;
    int gemm_blocks = (n + BM - 1) / BM;
    int scan_blocks = (n + 1023) / 1024;
    int gather_blocks = (n + NPW * 8 - 1) / (NPW * 8);   // one warp per NPW nodes

    // CSR + degree build (once per launch, reused by all 3 layers)
    zero_cnt_k<<<node_blocks, 256>>>(n);
    hist_k<<<edge_blocks, 256>>>(dst, e);
    dinv_k<<<node_blocks, 256>>>(n);
    scan1_k<<<scan_blocks, 1024>>>(n);
    scan2_k<<<1, 32>>>(scan_blocks);
    scan3_k<<<node_blocks, 256>>>(n);
    fill_k<<<edge_blocks, 256>>>(src, dst, e);

    // ---- layer 1 ----
    gemm_k<<<gemm_blocks, 256>>>(x, W1, n, 0);
    gather_k<0><<<gather_blocks, 256>>>(b1, nullptr, nullptr, nullptr, n);
    finalize_k<<<1, 128>>>(gn1w, gn1b, gn1a, n);

    // ---- layer 2 ----
    gemm_k<<<gemm_blocks, 256>>>(nullptr, W2, n, 1);
    gather_k<0><<<gather_blocks, 256>>>(b2, nullptr, nullptr, nullptr, n);
    finalize_k<<<1, 128>>>(gn2w, gn2b, gn2a, n);

    // ---- layer 3 ----
    gemm_k<<<gemm_blocks, 256>>>(nullptr, W3, n, 1);
    gather_k<1><<<gather_blocks, 256>>>(b3, Wout, bout, (float*)d_out, n);
}